// round 12
// baseline (speedup 1.0000x reference)
#include <cuda_runtime.h>
#include <cuda_bf16.h>
#include <cstdint>

#define N_TOTAL 557056
#define NC 64

// Scratch (device globals — no allocation allowed)
// g_m1/g_m2: MLP outputs TRANSPOSED per graph-block (c, i*n+j), PACKED u32:
//   low 16 bits = bf16 hi part, high 16 bits = bf16 lo part
__device__ uint32_t g_m1[N_TOTAL * NC];
__device__ uint32_t g_m2[N_TOTAL * NC];
__device__ float g_hs2[N_TOTAL * NC];   // holds h (spatial matmul result) only
// Pre-split, pre-swizzled weights: 7 matrices x 4096 bf16 (hi and lo), SW128 layout
__device__ uint4 g_wh4[7 * 512];
__device__ uint4 g_wl4[7 * 512];

__device__ __forceinline__ float4 ld4(const float* p) { return *reinterpret_cast<const float4*>(p); }
__device__ __forceinline__ void st4(float* p, float4 v) { *reinterpret_cast<float4*>(p) = v; }

__device__ __forceinline__ uint32_t smem_to_u32(const void* smem_ptr) {
    uint32_t addr;
    asm("{ .reg .u64 tmp; cvta.to.shared.u64 tmp, %1; cvt.u32.u64 %0, tmp; }"
        : "=r"(addr) : "l"(smem_ptr));
    return addr;
}
__device__ __forceinline__ uint32_t swz(uint32_t off) { return off ^ ((off >> 3) & 0x70); }

__device__ __forceinline__ uint32_t prmt(uint32_t a, uint32_t b, uint32_t sel) {
    uint32_t d;
    asm("prmt.b32 %0, %1, %2, %3;" : "=r"(d) : "r"(a), "r"(b), "r"(sel));
    return d;
}

// ===================== mma.sync / ldmatrix machinery =======================
__device__ __forceinline__ void ldsm_x4(uint32_t r[4], uint32_t addr) {
    asm volatile("ldmatrix.sync.aligned.m8n8.x4.shared.b16 {%0,%1,%2,%3}, [%4];"
                 : "=r"(r[0]), "=r"(r[1]), "=r"(r[2]), "=r"(r[3]) : "r"(addr));
}
__device__ __forceinline__ void ldsm_x4_t(uint32_t r[4], uint32_t addr) {
    asm volatile("ldmatrix.sync.aligned.m8n8.x4.trans.shared.b16 {%0,%1,%2,%3}, [%4];"
                 : "=r"(r[0]), "=r"(r[1]), "=r"(r[2]), "=r"(r[3]) : "r"(addr));
}
__device__ __forceinline__ void mma16816(float c[4], const uint32_t a[4], const uint32_t b[2]) {
    asm volatile("mma.sync.aligned.m16n8k16.row.col.f32.bf16.bf16.f32 "
                 "{%0,%1,%2,%3}, {%4,%5,%6,%7}, {%8,%9}, {%0,%1,%2,%3};"
                 : "+f"(c[0]), "+f"(c[1]), "+f"(c[2]), "+f"(c[3])
                 : "r"(a[0]), "r"(a[1]), "r"(a[2]), "r"(a[3]), "r"(b[0]), "r"(b[1]));
}

// bf16 two-term split of a float pair -> hpair{h0,h1}, lpair{l0,l1}
__device__ __forceinline__ void split2(float a, float b, uint32_t& h, uint32_t& l) {
    __nv_bfloat162 hh = __floats2bfloat162_rn(a, b);
    float la = a - __bfloat162float(hh.x);
    float lb = b - __bfloat162float(hh.y);
    __nv_bfloat162 ll = __floats2bfloat162_rn(la, lb);
    h = *reinterpret_cast<uint32_t*>(&hh);
    l = *reinterpret_cast<uint32_t*>(&ll);
}

// ===================== SMEM layout for kernels A and C =====================
#define OXH 0
#define OXL 16384
#define OHH 32768
#define OHL 49152
#define OBH 65536
#define OBL 73728
#define OPAR 81920
#define SMEM_BYTES 83968

// load B fragments (8 n-tiles) for one k16 step from a 64x64 bf16 SW128 tile
__device__ __forceinline__ void loadB(uint32_t bf[16], uint32_t sbW, int ks, int lane) {
    int rowB = (lane & 7) + ((lane >> 4) << 3);
    int chB = ks * 2 + ((lane >> 3) & 1);
#pragma unroll
    for (int t = 0; t < 4; t++) {
        uint32_t off = swz((uint32_t)((t * 16 + rowB) * 128 + chB * 16));
        ldsm_x4(bf + 4 * t, sbW + off);
    }
}

// warp GEMM: rows [wid*32, wid*32+32) x 64 cols, K=64, 3-term bf16 split
__device__ __forceinline__ void warp_gemm(uint32_t sb, int aHi, int aLo,
                                          float acc[2][8][4], int wid, int lane) {
#pragma unroll
    for (int m = 0; m < 2; m++)
#pragma unroll
        for (int nt = 0; nt < 8; nt++)
#pragma unroll
            for (int q = 0; q < 4; q++) acc[m][nt][q] = 0.f;

#pragma unroll
    for (int ks = 0; ks < 4; ks++) {
        uint32_t ah[2][4], al[2][4], bf[16];
        int rowA = wid * 32 + (lane & 15);
        int chA = ks * 2 + (lane >> 4);
        uint32_t offA0 = swz((uint32_t)(rowA * 128 + chA * 16));
        uint32_t offA1 = swz((uint32_t)((rowA + 16) * 128 + chA * 16));
        ldsm_x4(ah[0], sb + aHi + offA0);
        ldsm_x4(ah[1], sb + aHi + offA1);
        ldsm_x4(al[0], sb + aLo + offA0);
        ldsm_x4(al[1], sb + aLo + offA1);
        loadB(bf, sb + OBH, ks, lane);
#pragma unroll
        for (int m = 0; m < 2; m++)
#pragma unroll
            for (int p = 0; p < 4; p++) {
                mma16816(acc[m][2 * p], ah[m], &bf[4 * p]);
                mma16816(acc[m][2 * p], al[m], &bf[4 * p]);
                mma16816(acc[m][2 * p + 1], ah[m], &bf[4 * p + 2]);
                mma16816(acc[m][2 * p + 1], al[m], &bf[4 * p + 2]);
            }
        loadB(bf, sb + OBL, ks, lane);
#pragma unroll
        for (int m = 0; m < 2; m++)
#pragma unroll
            for (int p = 0; p < 4; p++) {
                mma16816(acc[m][2 * p], ah[m], &bf[4 * p]);
                mma16816(acc[m][2 * p + 1], ah[m], &bf[4 * p + 2]);
            }
    }
}

// copy pre-swizzled weight matrix m into OBH/OBL (8KB each)
__device__ __forceinline__ void copyW(char* sm, int m, int tid) {
#pragma unroll
    for (int i = 0; i < 4; i++) {
        int idx = i * 128 + tid;
        reinterpret_cast<uint4*>(sm + OBH)[idx] = g_wh4[m * 512 + idx];
        reinterpret_cast<uint4*>(sm + OBL)[idx] = g_wl4[m * 512 + idx];
    }
}

// convert 128 rows x 64 fp32 (row-major gmem) -> bf16 hi/lo SW128 smem tiles
__device__ __forceinline__ void convertX(char* sm, const float* __restrict__ src, int tid) {
#pragma unroll
    for (int i = 0; i < 8; i++) {
        int idx = i * 128 + tid;
        int r = idx >> 3, g = idx & 7;
        const float* p = src + r * 64 + g * 8;
        float4 f0 = ld4(p), f1 = ld4(p + 4);
        float vv[8] = {f0.x, f0.y, f0.z, f0.w, f1.x, f1.y, f1.z, f1.w};
        uint32_t hw[4], lw[4];
#pragma unroll
        for (int q = 0; q < 4; q++) split2(vv[2 * q], vv[2 * q + 1], hw[q], lw[q]);
        uint32_t off = swz((uint32_t)(r * 128 + g * 16));
        *reinterpret_cast<uint4*>(sm + OXH + off) = make_uint4(hw[0], hw[1], hw[2], hw[3]);
        *reinterpret_cast<uint4*>(sm + OXL + off) = make_uint4(lw[0], lw[1], lw[2], lw[3]);
    }
}

// ========================== setup: split weights ===========================
__global__ void kernelW(const float* __restrict__ w_m1, const float* __restrict__ w_m2,
                        const float* __restrict__ W_skip, const float* __restrict__ W_u1,
                        const float* __restrict__ W_u2) {
    int m = blockIdx.y;
    int idx = blockIdx.x * 256 + threadIdx.x;
    const float* W;
    switch (m) {
        case 0: W = w_m1; break;
        case 1: W = w_m1 + 4096; break;
        case 2: W = w_m2; break;
        case 3: W = w_m2 + 4096; break;
        case 4: W = W_skip; break;
        case 5: W = W_u1; break;
        default: W = W_u2; break;
    }
    float v = W[idx];
    int o = idx >> 6, k = idx & 63;
    __nv_bfloat16 h = __float2bfloat16(v);
    __nv_bfloat16 l = __float2bfloat16(v - __bfloat162float(h));
    uint32_t eoff = swz((uint32_t)(o * 128 + k * 2)) >> 1;
    reinterpret_cast<__nv_bfloat16*>(g_wh4)[m * 4096 + eoff] = h;
    reinterpret_cast<__nv_bfloat16*>(g_wl4)[m * 4096 + eoff] = l;
}

// ======= epilogue helpers =========
// store acc (+bias, relu) as split bf16 into HH/HL
__device__ __forceinline__ void epiH(char* sm, const float acc[2][8][4], const float* bias,
                                     int wid, int lane) {
    int g = lane >> 2, cb = (lane & 3) * 4;
#pragma unroll
    for (int m = 0; m < 2; m++)
#pragma unroll
        for (int rs = 0; rs < 2; rs++) {
            int row = wid * 32 + m * 16 + rs * 8 + g;
#pragma unroll
            for (int nt = 0; nt < 8; nt++) {
                int c = nt * 8 + (lane & 3) * 2;
                float v0 = fmaxf(acc[m][nt][rs * 2 + 0] + bias[c], 0.f);
                float v1 = fmaxf(acc[m][nt][rs * 2 + 1] + bias[c + 1], 0.f);
                uint32_t h, l;
                split2(v0, v1, h, l);
                uint32_t off = swz((uint32_t)(row * 128 + nt * 16 + cb));
                *reinterpret_cast<uint32_t*>(sm + OHH + off) = h;
                *reinterpret_cast<uint32_t*>(sm + OHL + off) = l;
            }
        }
}

// store acc (+bias, relu) TRANSPOSED per-block, PACKED u32 {bf16 hi | bf16 lo}
__device__ __forceinline__ void epiT(uint32_t* __restrict__ dst, int nsq, long localRow0,
                                     const float acc[2][8][4], const float* bias,
                                     int wid, int lane) {
    int g = lane >> 2;
#pragma unroll
    for (int m = 0; m < 2; m++)
#pragma unroll
        for (int rs = 0; rs < 2; rs++) {
            long rl = localRow0 + wid * 32 + m * 16 + rs * 8 + g;
#pragma unroll
            for (int nt = 0; nt < 8; nt++) {
                int c = nt * 8 + (lane & 3) * 2;
                float v0 = fmaxf(acc[m][nt][rs * 2 + 0] + bias[c], 0.f);
                float v1 = fmaxf(acc[m][nt][rs * 2 + 1] + bias[c + 1], 0.f);
                uint32_t hp, lp;
                split2(v0, v1, hp, lp);
                dst[(long)c * nsq + rl] = prmt(hp, lp, 0x5410u);       // {h0, l0}
                dst[(long)(c + 1) * nsq + rl] = prmt(hp, lp, 0x7632u); // {h1, l1}
            }
        }
}

// =============== Kernel A: x -> m1t, m2t (2-layer MLPs) ====================
__global__ void __launch_bounds__(128) kernelA(
    const float* __restrict__ x,
    const float* __restrict__ b_m1, const float* __restrict__ b_m2) {
    extern __shared__ char sm[];
    uint32_t sb = smem_to_u32(sm);
    int tid = threadIdx.x, wid = tid >> 5, lane = tid & 31;
    long row0 = (long)blockIdx.x * 128;
    float* par = reinterpret_cast<float*>(sm + OPAR);

    // bucket mapping (all 128 rows lie in one graph-block: n^2 % 128 == 0)
    int n_, nsq;
    long bbase;
    if (row0 < 131072L)      { n_ = 32; bbase = 0L; }
    else if (row0 < 278528L) { n_ = 48; bbase = 131072L; }
    else if (row0 < 409600L) { n_ = 64; bbase = 278528L; }
    else                     { n_ = 96; bbase = 409600L; }
    nsq = n_ * n_;
    long blk_start = bbase + ((row0 - bbase) / nsq) * nsq;
    long localRow0 = row0 - blk_start;
    uint32_t* d1 = g_m1 + blk_start * 64;
    uint32_t* d2 = g_m2 + blk_start * 64;

    if (tid < 64) {
        par[tid] = b_m1[tid];
        par[64 + tid] = b_m1[64 + tid];
        par[128 + tid] = b_m2[tid];
        par[192 + tid] = b_m2[64 + tid];
    }
    convertX(sm, x + row0 * 64, tid);
    copyW(sm, 0, tid);
    __syncthreads();

    float acc[2][8][4];

    // GEMM1: X @ Wm1_0 -> H (relu)
    warp_gemm(sb, OXH, OXL, acc, wid, lane);
    __syncthreads();
    epiH(sm, acc, par, wid, lane);
    copyW(sm, 1, tid);
    __syncthreads();

    // GEMM2: H @ Wm1_1 -> g_m1 transposed packed (relu)
    warp_gemm(sb, OHH, OHL, acc, wid, lane);
    __syncthreads();
    epiT(d1, nsq, localRow0, acc, par + 64, wid, lane);
    copyW(sm, 2, tid);
    __syncthreads();

    // GEMM3: X @ Wm2_0 -> H (relu)
    warp_gemm(sb, OXH, OXL, acc, wid, lane);
    __syncthreads();
    epiH(sm, acc, par + 128, wid, lane);
    copyW(sm, 3, tid);
    __syncthreads();

    // GEMM4: H @ Wm2_1 -> g_m2 transposed packed (relu)
    warp_gemm(sb, OHH, OHL, acc, wid, lane);
    __syncthreads();
    epiT(d2, nsq, localRow0, acc, par + 192, wid, lane);
}

// ---------------------------------------------------------------------------
// Kernel B (tensor-core): per-graph-block, per-channel spatial matmul
//   h[b,i,k,c] = sum_j m1[b,i,j,c]*m2[b,j,k,c];  g_hs2 = h (PURE STORE, no RMW)
// CTA = (block b, 32x32 i/k tile, 8 channels). Warp w owns channel w.
// A/B tiles arrive PACKED u32 {hi|lo}; staging = LDG + 2 PRMT per pair -> hi/lo
// smem tiles (SW128, 2 rows per 128B). smem: Ah @0, Al @16K, Bh @32K, Bl @48K;
// Cs (fp32 [8][32][33]) reuses @0 after the mainloop.
// ---------------------------------------------------------------------------
#define BAH 0
#define BAL 16384
#define BBH 32768
#define BBL 49152

template <int N>
__global__ void __launch_bounds__(256) kernelB(long baseRow) {
    constexpr int NT = (N + 31) / 32;
    extern __shared__ char sm[];
    uint32_t sb = smem_to_u32(sm);
    int t = threadIdx.x, lane = t & 31, wid = t >> 5;
    int b = blockIdx.x;
    int ti = blockIdx.y / NT, tk = blockIdx.y % NT;
    int cg = blockIdx.z;                       // channel group 0..7 (8 ch each)
    int i0 = ti * 32, k0 = tk * 32;
    long blk = baseRow + (long)b * (N * N);
    const uint32_t* m1p = g_m1 + blk * 64;
    const uint32_t* m2p = g_m2 + blk * 64;

    int sr = t & 31, sch = t >> 5;             // staging: row, channel
    long chbase = (long)(cg * 8 + sch) * (N * N);
    uint32_t rowoff = (uint32_t)((sr >> 1) * 128 + (sr & 1) * 64);
    uint32_t sA = (uint32_t)(sch * 2048);
    const int nk = (k0 + 32 <= N) ? 32 : (N - k0);

    float acc[2][4][4];
#pragma unroll
    for (int m = 0; m < 2; m++)
#pragma unroll
        for (int n8 = 0; n8 < 4; n8++)
#pragma unroll
            for (int q = 0; q < 4; q++) acc[m][n8][q] = 0.f;

    const bool iok = (i0 + sr < N);
    const long arow = chbase + (long)(i0 + sr) * N;

#pragma unroll
    for (int jc = 0; jc < NT; jc++) {
        const int j0 = jc * 32;
        const int nj = (j0 + 32 <= N) ? 32 : (N - j0);
        __syncthreads();
        // ---- stage A (i-rows, j-window): packed u32 -> PRMT -> hi/lo ----
        {
            uint4 f[8];
#pragma unroll
            for (int q = 0; q < 8; q++) f[q] = make_uint4(0u, 0u, 0u, 0u);
            if (iok) {
                const uint32_t* p = m1p + arow + j0;
#pragma unroll
                for (int q = 0; q < 8; q++)
                    if (q * 4 < nj) f[q] = *reinterpret_cast<const uint4*>(p + q * 4);
            }
            uint32_t h[16], l[16];
#pragma unroll
            for (int q = 0; q < 8; q++) {
                h[2 * q] = prmt(f[q].x, f[q].y, 0x5410u);
                l[2 * q] = prmt(f[q].x, f[q].y, 0x7632u);
                h[2 * q + 1] = prmt(f[q].z, f[q].w, 0x5410u);
                l[2 * q + 1] = prmt(f[q].z, f[q].w, 0x7632u);
            }
#pragma unroll
            for (int g = 0; g < 4; g++) {
                uint32_t off = sA + swz(rowoff + g * 16);
                *reinterpret_cast<uint4*>(sm + BAH + off) =
                    make_uint4(h[4 * g], h[4 * g + 1], h[4 * g + 2], h[4 * g + 3]);
                *reinterpret_cast<uint4*>(sm + BAL + off) =
                    make_uint4(l[4 * g], l[4 * g + 1], l[4 * g + 2], l[4 * g + 3]);
            }
        }
        // ---- stage B (j-rows, k-window) ----
        {
            uint4 f[8];
#pragma unroll
            for (int q = 0; q < 8; q++) f[q] = make_uint4(0u, 0u, 0u, 0u);
            if (j0 + sr < N) {
                const uint32_t* p = m2p + chbase + (long)(j0 + sr) * N + k0;
#pragma unroll
                for (int q = 0; q < 8; q++)
                    if (q * 4 < nk) f[q] = *reinterpret_cast<const uint4*>(p + q * 4);
            }
            uint32_t h[16], l[16];
#pragma unroll
            for (int q = 0; q < 8; q++) {
                h[2 * q] = prmt(f[q].x, f[q].y, 0x5410u);
                l[2 * q] = prmt(f[q].x, f[q].y, 0x7632u);
                h[2 * q + 1] = prmt(f[q].z, f[q].w, 0x5410u);
                l[2 * q + 1] = prmt(f[q].z, f[q].w, 0x7632u);
            }
#pragma unroll
            for (int g = 0; g < 4; g++) {
                uint32_t off = sA + swz(rowoff + g * 16);
                *reinterpret_cast<uint4*>(sm + BBH + off) =
                    make_uint4(h[4 * g], h[4 * g + 1], h[4 * g + 2], h[4 * g + 3]);
                *reinterpret_cast<uint4*>(sm + BBL + off) =
                    make_uint4(l[4 * g], l[4 * g + 1], l[4 * g + 2], l[4 * g + 3]);
            }
        }
        __syncthreads();
        // ---- MMA: warp wid computes channel wid's 32x32 tile over K=32 ----
        {
            uint32_t aH = sb + BAH + wid * 2048, aL = sb + BAL + wid * 2048;
            uint32_t bH = sb + BBH + wid * 2048, bL = sb + BBL + wid * 2048;
#pragma unroll
            for (int ks = 0; ks < 2; ks++) {
                uint32_t ah[2][4], al[2][4];
#pragma unroll
                for (int m = 0; m < 2; m++) {
                    int ri = m * 16 + (lane & 15);
                    uint32_t offA = swz((uint32_t)((ri >> 1) * 128 + (ri & 1) * 64 +
                                                   (ks * 2 + (lane >> 4)) * 16));
                    ldsm_x4(ah[m], aH + offA);
                    ldsm_x4(al[m], aL + offA);
                }
#pragma unroll
                for (int nb = 0; nb < 2; nb++) {
                    int jr = ks * 16 + (lane & 15);
                    uint32_t offB = swz((uint32_t)((jr >> 1) * 128 + (jr & 1) * 64 +
                                                   (nb * 2 + (lane >> 4)) * 16));
                    uint32_t bh[4], bl[4];
                    ldsm_x4_t(bh, bH + offB);
                    ldsm_x4_t(bl, bL + offB);
#pragma unroll
                    for (int m = 0; m < 2; m++) {
                        mma16816(acc[m][nb * 2 + 0], ah[m], &bh[0]);
                        mma16816(acc[m][nb * 2 + 0], al[m], &bh[0]);
                        mma16816(acc[m][nb * 2 + 0], ah[m], &bl[0]);
                        mma16816(acc[m][nb * 2 + 1], ah[m], &bh[2]);
                        mma16816(acc[m][nb * 2 + 1], al[m], &bh[2]);
                        mma16816(acc[m][nb * 2 + 1], ah[m], &bl[2]);
                    }
                }
            }
        }
    }
    __syncthreads();
    // ---- stage C tiles (fp32) into smem: Cs[ch][i][k], stride 33 ----
    float* Cs = reinterpret_cast<float*>(sm);
    {
        int g = lane >> 2, cbl = (lane & 3) * 2;
#pragma unroll
        for (int m = 0; m < 2; m++)
#pragma unroll
            for (int n8 = 0; n8 < 4; n8++)
#pragma unroll
                for (int rs = 0; rs < 2; rs++) {
                    int r = m * 16 + rs * 8 + g;
                    Cs[wid * 1056 + r * 33 + n8 * 8 + cbl + 0] = acc[m][n8][rs * 2 + 0];
                    Cs[wid * 1056 + r * 33 + n8 * 8 + cbl + 1] = acc[m][n8][rs * 2 + 1];
                }
    }
    __syncthreads();
    // ---- PURE coalesced store into g_hs2 (no RMW): 8 ch = 32B sector ----
#pragma unroll
    for (int it = 0; it < 4; it++) {
        int ik = it * 256 + t;
        int i = ik >> 5, k = ik & 31;
        if (i0 + i < N && k0 + k < N) {
            float* p = g_hs2 + (blk + (long)(i0 + i) * N + (k0 + k)) * 64 + cg * 8;
            float v[8];
#pragma unroll
            for (int ch = 0; ch < 8; ch++) v[ch] = Cs[ch * 1056 + i * 33 + k];
            st4(p, make_float4(v[0], v[1], v[2], v[3]));
            st4(p + 4, make_float4(v[4], v[5], v[6], v[7]));
        }
    }
}

// ==== Kernel C: hs2 = h + x@Wskip+b; Lin+BN+ReLU x2; out = u + hs2 =========
__global__ void __launch_bounds__(128) kernelC(
    const float* __restrict__ x, const float* __restrict__ b_skip,
    const float* __restrict__ b_u1, const float* __restrict__ g1,
    const float* __restrict__ beta1, const float* __restrict__ rm1,
    const float* __restrict__ rv1,
    const float* __restrict__ b_u2, const float* __restrict__ g2,
    const float* __restrict__ beta2, const float* __restrict__ rm2,
    const float* __restrict__ rv2,
    float* __restrict__ out) {
    extern __shared__ char sm[];
    uint32_t sb = smem_to_u32(sm);
    int tid = threadIdx.x, wid = tid >> 5, lane = tid & 31;
    long row0 = (long)blockIdx.x * 128;
    float* par = reinterpret_cast<float*>(sm + OPAR);
    float* Hs2 = reinterpret_cast<float*>(sm + OHH);   // 128x64 fp32, XOR-swizzled

    if (tid < 64) {
        par[tid] = b_u1[tid];
        float sc1 = g1[tid] * rsqrtf(rv1[tid] + 1e-5f);
        par[64 + tid] = sc1;
        par[128 + tid] = beta1[tid] - rm1[tid] * sc1;
        par[192 + tid] = b_u2[tid];
        float sc2 = g2[tid] * rsqrtf(rv2[tid] + 1e-5f);
        par[256 + tid] = sc2;
        par[320 + tid] = beta2[tid] - rm2[tid] * sc2;
        par[384 + tid] = b_skip[tid];
    }
    convertX(sm, x + row0 * 64, tid);
    copyW(sm, 4, tid);   // W_skip
    // stage h tile (128x64 fp32 = 2048 float4) coalesced into OHH/OHL region,
    // XOR-swizzled: addr(r, c) = r*64 + (c ^ ((r&7)*8))   (float units)
#pragma unroll
    for (int i = 0; i < 16; i++) {
        int fidx = i * 128 + tid;            // float4 slot 0..2047
        int r = fidx >> 4, q = fidx & 15;
        float4 v = ld4(g_hs2 + (row0 + r) * 64 + q * 4);
        *reinterpret_cast<float4*>(&Hs2[r * 64 + ((q * 4) ^ ((r & 7) * 8))]) = v;
    }
    __syncthreads();

    float acc[2][8][4];

    // GEMM0: x @ W_skip -> acc; then hs2 = acc + b_skip + h (from smem)
    warp_gemm(sb, OXH, OXL, acc, wid, lane);
    {
        int g = lane >> 2;
#pragma unroll
        for (int m = 0; m < 2; m++)
#pragma unroll
            for (int rs = 0; rs < 2; rs++) {
                int row = wid * 32 + m * 16 + rs * 8 + g;
#pragma unroll
                for (int nt = 0; nt < 8; nt++) {
                    int c = nt * 8 + (lane & 3) * 2;
                    float2 hv = *reinterpret_cast<const float2*>(
                        &Hs2[row * 64 + (c ^ ((row & 7) * 8))]);
                    acc[m][nt][rs * 2 + 0] += par[384 + c] + hv.x;
                    acc[m][nt][rs * 2 + 1] += par[384 + c + 1] + hv.y;
                }
            }
    }
    __syncthreads();   // all warps done reading X tiles + Hs2 before overwrite
    // store hs2 (no relu) into OXH/OXL as split bf16 (GEMM1 input + residual)
    {
        int g = lane >> 2, cb = (lane & 3) * 4;
#pragma unroll
        for (int m = 0; m < 2; m++)
#pragma unroll
            for (int rs = 0; rs < 2; rs++) {
                int row = wid * 32 + m * 16 + rs * 8 + g;
#pragma unroll
                for (int nt = 0; nt < 8; nt++) {
                    uint32_t h, l;
                    split2(acc[m][nt][rs * 2 + 0], acc[m][nt][rs * 2 + 1], h, l);
                    uint32_t off = swz((uint32_t)(row * 128 + nt * 16 + cb));
                    *reinterpret_cast<uint32_t*>(sm + OXH + off) = h;
                    *reinterpret_cast<uint32_t*>(sm + OXL + off) = l;
                }
            }
    }
    copyW(sm, 5, tid);   // W_u1
    __syncthreads();

    // GEMM1: hs2 @ W_u1 -> H = relu(bn1(. + b_u1))
    warp_gemm(sb, OXH, OXL, acc, wid, lane);
    __syncthreads();
    {
        int g = lane >> 2, cb = (lane & 3) * 4;
#pragma unroll
        for (int m = 0; m < 2; m++)
#pragma unroll
            for (int rs = 0; rs < 2; rs++) {
                int row = wid * 32 + m * 16 + rs * 8 + g;
#pragma unroll
                for (int nt = 0; nt < 8; nt++) {
                    int c = nt * 8 + (lane & 3) * 2;
                    float v0 = fmaxf((acc[m][nt][rs * 2 + 0] + par[c]) * par[64 + c] + par[128 + c], 0.f);
                    float v1 = fmaxf((acc[m][nt][rs * 2 + 1] + par[c + 1]) * par[64 + c + 1] + par[128 + c + 1], 0.f);
                    uint32_t h, l;
                    split2(v0, v1, h, l);
                    uint32_t off = swz((uint32_t)(row * 128 + nt * 16 + cb));
                    *reinterpret_cast<uint32_t*>(sm + OHH + off) = h;
                    *reinterpret_cast<uint32_t*>(sm + OHL + off) = l;
                }
            }
    }
    copyW(sm, 6, tid);   // W_u2
    __syncthreads();

    // GEMM2: H @ W_u2 -> out = relu(bn2(. + b_u2)) + hs2
    warp_gemm(sb, OHH, OHL, acc, wid, lane);
    {
        int g = lane >> 2, cb = (lane & 3) * 4;
#pragma unroll
        for (int m = 0; m < 2; m++)
#pragma unroll
            for (int rs = 0; rs < 2; rs++) {
                int row = wid * 32 + m * 16 + rs * 8 + g;
                long grow = row0 + row;
#pragma unroll
                for (int nt = 0; nt < 8; nt++) {
                    int c = nt * 8 + (lane & 3) * 2;
                    float u0 = fmaxf((acc[m][nt][rs * 2 + 0] + par[192 + c]) * par[256 + c] + par[320 + c], 0.f);
                    float u1 = fmaxf((acc[m][nt][rs * 2 + 1] + par[192 + c + 1]) * par[256 + c + 1] + par[320 + c + 1], 0.f);
                    uint32_t off = swz((uint32_t)(row * 128 + nt * 16 + cb));
                    uint32_t xh = *reinterpret_cast<uint32_t*>(sm + OXH + off);
                    uint32_t xl = *reinterpret_cast<uint32_t*>(sm + OXL + off);
                    float2 h2 = __bfloat1622float2(*reinterpret_cast<__nv_bfloat162*>(&xh));
                    float2 l2 = __bfloat1622float2(*reinterpret_cast<__nv_bfloat162*>(&xl));
                    *reinterpret_cast<float2*>(out + grow * 64 + c) =
                        make_float2(u0 + (h2.x + l2.x), u1 + (h2.y + l2.y));
                }
            }
    }
}

// ---------------------------------------------------------------------------
extern "C" void kernel_launch(void* const* d_in, const int* in_sizes, int n_in,
                              void* d_out, int out_size) {
    (void)in_sizes; (void)n_in; (void)out_size;
    const float* x      = (const float*)d_in[0];
    const float* w_m1   = (const float*)d_in[1];
    const float* b_m1   = (const float*)d_in[2];
    const float* w_m2   = (const float*)d_in[3];
    const float* b_m2   = (const float*)d_in[4];
    const float* W_skip = (const float*)d_in[5];
    const float* b_skip = (const float*)d_in[6];
    const float* W_u1   = (const float*)d_in[7];
    const float* b_u1   = (const float*)d_in[8];
    const float* g1     = (const float*)d_in[9];
    const float* beta1  = (const float*)d_in[10];
    const float* rm1    = (const float*)d_in[11];
    const float* rv1    = (const float*)d_in[12];
    const float* W_u2   = (const float*)d_in[13];
    const float* b_u2   = (const float*)d_in[14];
    const float* g2     = (const float*)d_in[15];
    const float* beta2  = (const float*)d_in[16];
    const float* rm2    = (const float*)d_in[17];
    const float* rv2    = (const float*)d_in[18];
    float* out = (float*)d_out;

    cudaFuncSetAttribute(kernelA, cudaFuncAttributeMaxDynamicSharedMemorySize, SMEM_BYTES);
    cudaFuncSetAttribute(kernelC, cudaFuncAttributeMaxDynamicSharedMemorySize, SMEM_BYTES);
    cudaFuncSetAttribute(kernelB<32>, cudaFuncAttributeMaxDynamicSharedMemorySize, 65536);
    cudaFuncSetAttribute(kernelB<48>, cudaFuncAttributeMaxDynamicSharedMemorySize, 65536);
    cudaFuncSetAttribute(kernelB<64>, cudaFuncAttributeMaxDynamicSharedMemorySize, 65536);
    cudaFuncSetAttribute(kernelB<96>, cudaFuncAttributeMaxDynamicSharedMemorySize, 65536);

    kernelW<<<dim3(16, 7), 256>>>(w_m1, w_m2, W_skip, W_u1, W_u2);

    kernelA<<<N_TOTAL / 128, 128, SMEM_BYTES>>>(x, b_m1, b_m2);

    // BLOCKS = [(128,32),(64,48),(32,64),(16,96)], row bases 0/131072/278528/409600
    kernelB<32><<<dim3(128, 1, 8), 256, 65536>>>(0L);
    kernelB<48><<<dim3(64, 4, 8), 256, 65536>>>(131072L);
    kernelB<64><<<dim3(32, 4, 8), 256, 65536>>>(278528L);
    kernelB<96><<<dim3(16, 9, 8), 256, 65536>>>(409600L);

    kernelC<<<N_TOTAL / 128, 128, SMEM_BYTES>>>(x, b_skip, b_u1, g1, beta1, rm1, rv1,
                                                b_u2, g2, beta2, rm2, rv2, out);
}

// round 13
// speedup vs baseline: 1.0520x; 1.0520x over previous
#include <cuda_runtime.h>
#include <cuda_bf16.h>
#include <cstdint>

#define N_TOTAL 557056
#define NC 64

// Scratch (device globals — no allocation allowed)
// g_m1/g_m2: MLP outputs TRANSPOSED per graph-block (c, i*n+j), fp32
__device__ float g_m1[N_TOTAL * NC];
__device__ float g_m2[N_TOTAL * NC];
__device__ float g_hs2[N_TOTAL * NC];   // holds h (spatial matmul result) only
// Pre-split, pre-swizzled weights: 7 matrices x 4096 bf16 (hi and lo), SW128 layout
__device__ uint4 g_wh4[7 * 512];
__device__ uint4 g_wl4[7 * 512];

__device__ __forceinline__ float4 ld4(const float* p) { return *reinterpret_cast<const float4*>(p); }
__device__ __forceinline__ void st4(float* p, float4 v) { *reinterpret_cast<float4*>(p) = v; }

__device__ __forceinline__ uint32_t smem_to_u32(const void* smem_ptr) {
    uint32_t addr;
    asm("{ .reg .u64 tmp; cvta.to.shared.u64 tmp, %1; cvt.u32.u64 %0, tmp; }"
        : "=r"(addr) : "l"(smem_ptr));
    return addr;
}
__device__ __forceinline__ uint32_t swz(uint32_t off) { return off ^ ((off >> 3) & 0x70); }

// ===================== mma.sync / ldmatrix machinery =======================
__device__ __forceinline__ void ldsm_x4(uint32_t r[4], uint32_t addr) {
    asm volatile("ldmatrix.sync.aligned.m8n8.x4.shared.b16 {%0,%1,%2,%3}, [%4];"
                 : "=r"(r[0]), "=r"(r[1]), "=r"(r[2]), "=r"(r[3]) : "r"(addr));
}
__device__ __forceinline__ void ldsm_x4_t(uint32_t r[4], uint32_t addr) {
    asm volatile("ldmatrix.sync.aligned.m8n8.x4.trans.shared.b16 {%0,%1,%2,%3}, [%4];"
                 : "=r"(r[0]), "=r"(r[1]), "=r"(r[2]), "=r"(r[3]) : "r"(addr));
}
__device__ __forceinline__ void mma16816(float c[4], const uint32_t a[4], const uint32_t b[2]) {
    asm volatile("mma.sync.aligned.m16n8k16.row.col.f32.bf16.bf16.f32 "
                 "{%0,%1,%2,%3}, {%4,%5,%6,%7}, {%8,%9}, {%0,%1,%2,%3};"
                 : "+f"(c[0]), "+f"(c[1]), "+f"(c[2]), "+f"(c[3])
                 : "r"(a[0]), "r"(a[1]), "r"(a[2]), "r"(a[3]), "r"(b[0]), "r"(b[1]));
}

// bf16 two-term split of a float pair
__device__ __forceinline__ void split2(float a, float b, uint32_t& h, uint32_t& l) {
    __nv_bfloat162 hh = __floats2bfloat162_rn(a, b);
    float la = a - __bfloat162float(hh.x);
    float lb = b - __bfloat162float(hh.y);
    __nv_bfloat162 ll = __floats2bfloat162_rn(la, lb);
    h = *reinterpret_cast<uint32_t*>(&hh);
    l = *reinterpret_cast<uint32_t*>(&ll);
}

// ===================== SMEM layout for kernels A and C =====================
#define OXH 0
#define OXL 16384
#define OHH 32768
#define OHL 49152
#define OBH 65536
#define OBL 73728
#define OPAR 81920
#define SMEM_BYTES 83968

// load B fragments (8 n-tiles) for one k16 step from a 64x64 bf16 SW128 tile
__device__ __forceinline__ void loadB(uint32_t bf[16], uint32_t sbW, int ks, int lane) {
    int rowB = (lane & 7) + ((lane >> 4) << 3);
    int chB = ks * 2 + ((lane >> 3) & 1);
#pragma unroll
    for (int t = 0; t < 4; t++) {
        uint32_t off = swz((uint32_t)((t * 16 + rowB) * 128 + chB * 16));
        ldsm_x4(bf + 4 * t, sbW + off);
    }
}

// warp GEMM: rows [wid*32, wid*32+32) x 64 cols, K=64, 3-term bf16 split
__device__ __forceinline__ void warp_gemm(uint32_t sb, int aHi, int aLo,
                                          float acc[2][8][4], int wid, int lane) {
#pragma unroll
    for (int m = 0; m < 2; m++)
#pragma unroll
        for (int nt = 0; nt < 8; nt++)
#pragma unroll
            for (int q = 0; q < 4; q++) acc[m][nt][q] = 0.f;

#pragma unroll
    for (int ks = 0; ks < 4; ks++) {
        uint32_t ah[2][4], al[2][4], bf[16];
        int rowA = wid * 32 + (lane & 15);
        int chA = ks * 2 + (lane >> 4);
        uint32_t offA0 = swz((uint32_t)(rowA * 128 + chA * 16));
        uint32_t offA1 = swz((uint32_t)((rowA + 16) * 128 + chA * 16));
        ldsm_x4(ah[0], sb + aHi + offA0);
        ldsm_x4(ah[1], sb + aHi + offA1);
        ldsm_x4(al[0], sb + aLo + offA0);
        ldsm_x4(al[1], sb + aLo + offA1);
        loadB(bf, sb + OBH, ks, lane);
#pragma unroll
        for (int m = 0; m < 2; m++)
#pragma unroll
            for (int p = 0; p < 4; p++) {
                mma16816(acc[m][2 * p], ah[m], &bf[4 * p]);
                mma16816(acc[m][2 * p], al[m], &bf[4 * p]);
                mma16816(acc[m][2 * p + 1], ah[m], &bf[4 * p + 2]);
                mma16816(acc[m][2 * p + 1], al[m], &bf[4 * p + 2]);
            }
        loadB(bf, sb + OBL, ks, lane);
#pragma unroll
        for (int m = 0; m < 2; m++)
#pragma unroll
            for (int p = 0; p < 4; p++) {
                mma16816(acc[m][2 * p], ah[m], &bf[4 * p]);
                mma16816(acc[m][2 * p + 1], ah[m], &bf[4 * p + 2]);
            }
    }
}

// copy pre-swizzled weight matrix m into OBH/OBL (8KB each)
__device__ __forceinline__ void copyW(char* sm, int m, int tid) {
#pragma unroll
    for (int i = 0; i < 4; i++) {
        int idx = i * 128 + tid;
        reinterpret_cast<uint4*>(sm + OBH)[idx] = g_wh4[m * 512 + idx];
        reinterpret_cast<uint4*>(sm + OBL)[idx] = g_wl4[m * 512 + idx];
    }
}

// convert 128 rows x 64 fp32 (row-major gmem) -> bf16 hi/lo SW128 smem tiles
__device__ __forceinline__ void convertX(char* sm, const float* __restrict__ src, int tid) {
#pragma unroll
    for (int i = 0; i < 8; i++) {
        int idx = i * 128 + tid;
        int r = idx >> 3, g = idx & 7;
        const float* p = src + r * 64 + g * 8;
        float4 f0 = ld4(p), f1 = ld4(p + 4);
        float vv[8] = {f0.x, f0.y, f0.z, f0.w, f1.x, f1.y, f1.z, f1.w};
        uint32_t hw[4], lw[4];
#pragma unroll
        for (int q = 0; q < 4; q++) split2(vv[2 * q], vv[2 * q + 1], hw[q], lw[q]);
        uint32_t off = swz((uint32_t)(r * 128 + g * 16));
        *reinterpret_cast<uint4*>(sm + OXH + off) = make_uint4(hw[0], hw[1], hw[2], hw[3]);
        *reinterpret_cast<uint4*>(sm + OXL + off) = make_uint4(lw[0], lw[1], lw[2], lw[3]);
    }
}

// ========================== setup: split weights ===========================
__global__ void kernelW(const float* __restrict__ w_m1, const float* __restrict__ w_m2,
                        const float* __restrict__ W_skip, const float* __restrict__ W_u1,
                        const float* __restrict__ W_u2) {
    int m = blockIdx.y;
    int idx = blockIdx.x * 256 + threadIdx.x;
    const float* W;
    switch (m) {
        case 0: W = w_m1; break;
        case 1: W = w_m1 + 4096; break;
        case 2: W = w_m2; break;
        case 3: W = w_m2 + 4096; break;
        case 4: W = W_skip; break;
        case 5: W = W_u1; break;
        default: W = W_u2; break;
    }
    float v = W[idx];
    int o = idx >> 6, k = idx & 63;
    __nv_bfloat16 h = __float2bfloat16(v);
    __nv_bfloat16 l = __float2bfloat16(v - __bfloat162float(h));
    uint32_t eoff = swz((uint32_t)(o * 128 + k * 2)) >> 1;
    reinterpret_cast<__nv_bfloat16*>(g_wh4)[m * 4096 + eoff] = h;
    reinterpret_cast<__nv_bfloat16*>(g_wl4)[m * 4096 + eoff] = l;
}

// ======= epilogue helpers =========
// store acc (+bias, relu) as split bf16 into HH/HL
__device__ __forceinline__ void epiH(char* sm, const float acc[2][8][4], const float* bias,
                                     int wid, int lane) {
    int g = lane >> 2, cb = (lane & 3) * 4;
#pragma unroll
    for (int m = 0; m < 2; m++)
#pragma unroll
        for (int rs = 0; rs < 2; rs++) {
            int row = wid * 32 + m * 16 + rs * 8 + g;
#pragma unroll
            for (int nt = 0; nt < 8; nt++) {
                int c = nt * 8 + (lane & 3) * 2;
                float v0 = fmaxf(acc[m][nt][rs * 2 + 0] + bias[c], 0.f);
                float v1 = fmaxf(acc[m][nt][rs * 2 + 1] + bias[c + 1], 0.f);
                uint32_t h, l;
                split2(v0, v1, h, l);
                uint32_t off = swz((uint32_t)(row * 128 + nt * 16 + cb));
                *reinterpret_cast<uint32_t*>(sm + OHH + off) = h;
                *reinterpret_cast<uint32_t*>(sm + OHL + off) = l;
            }
        }
}

// store acc (+bias, relu) TRANSPOSED per-block: dst[(c)*nsq + localRow], fp32
__device__ __forceinline__ void epiT(float* __restrict__ dst, int nsq, long localRow0,
                                     const float acc[2][8][4], const float* bias,
                                     int wid, int lane) {
    int g = lane >> 2;
#pragma unroll
    for (int m = 0; m < 2; m++)
#pragma unroll
        for (int rs = 0; rs < 2; rs++) {
            long rl = localRow0 + wid * 32 + m * 16 + rs * 8 + g;
#pragma unroll
            for (int nt = 0; nt < 8; nt++) {
                int c = nt * 8 + (lane & 3) * 2;
                dst[(long)c * nsq + rl] = fmaxf(acc[m][nt][rs * 2 + 0] + bias[c], 0.f);
                dst[(long)(c + 1) * nsq + rl] = fmaxf(acc[m][nt][rs * 2 + 1] + bias[c + 1], 0.f);
            }
        }
}

// =============== Kernel A: x -> m1t, m2t (2-layer MLPs) ====================
__global__ void __launch_bounds__(128) kernelA(
    const float* __restrict__ x,
    const float* __restrict__ b_m1, const float* __restrict__ b_m2) {
    extern __shared__ char sm[];
    uint32_t sb = smem_to_u32(sm);
    int tid = threadIdx.x, wid = tid >> 5, lane = tid & 31;
    long row0 = (long)blockIdx.x * 128;
    float* par = reinterpret_cast<float*>(sm + OPAR);

    // bucket mapping (all 128 rows lie in one graph-block: n^2 % 128 == 0)
    int n_, nsq;
    long bbase;
    if (row0 < 131072L)      { n_ = 32; bbase = 0L; }
    else if (row0 < 278528L) { n_ = 48; bbase = 131072L; }
    else if (row0 < 409600L) { n_ = 64; bbase = 278528L; }
    else                     { n_ = 96; bbase = 409600L; }
    nsq = n_ * n_;
    long blk_start = bbase + ((row0 - bbase) / nsq) * nsq;
    long localRow0 = row0 - blk_start;
    float* d1 = g_m1 + blk_start * 64;
    float* d2 = g_m2 + blk_start * 64;

    if (tid < 64) {
        par[tid] = b_m1[tid];
        par[64 + tid] = b_m1[64 + tid];
        par[128 + tid] = b_m2[tid];
        par[192 + tid] = b_m2[64 + tid];
    }
    convertX(sm, x + row0 * 64, tid);
    copyW(sm, 0, tid);
    __syncthreads();

    float acc[2][8][4];

    // GEMM1: X @ Wm1_0 -> H (relu)
    warp_gemm(sb, OXH, OXL, acc, wid, lane);
    __syncthreads();
    epiH(sm, acc, par, wid, lane);
    copyW(sm, 1, tid);
    __syncthreads();

    // GEMM2: H @ Wm1_1 -> g_m1 transposed (relu)
    warp_gemm(sb, OHH, OHL, acc, wid, lane);
    __syncthreads();
    epiT(d1, nsq, localRow0, acc, par + 64, wid, lane);
    copyW(sm, 2, tid);
    __syncthreads();

    // GEMM3: X @ Wm2_0 -> H (relu)
    warp_gemm(sb, OXH, OXL, acc, wid, lane);
    __syncthreads();
    epiH(sm, acc, par + 128, wid, lane);
    copyW(sm, 3, tid);
    __syncthreads();

    // GEMM4: H @ Wm2_1 -> g_m2 transposed (relu)
    warp_gemm(sb, OHH, OHL, acc, wid, lane);
    __syncthreads();
    epiT(d2, nsq, localRow0, acc, par + 192, wid, lane);
}

// ---------------------------------------------------------------------------
// Kernel B (tensor-core, FUSED single launch): per-block spatial matmul
//   h[b,i,k,c] = sum_j m1[b,i,j,c]*m2[b,j,k,c];  g_hs2 = h (PURE STORE)
// CTA = (block b, 32x32 i/k tile, 8 channels). Warp w owns channel w.
// A/B tiles staged as bf16 hi/lo (split in-kernel from fp32), SW128,
// 2 rows packed per 128B. smem: Ah @0, Al @16K, Bh @32K, Bl @48K;
// Cs (fp32 [8][32][33]) reuses @0 after the mainloop.
// All four N variants dispatched from one grid (longest variant first).
// ---------------------------------------------------------------------------
#define BAH 0
#define BAL 16384
#define BBH 32768
#define BBL 49152

template <int N>
__device__ __forceinline__ void runB(char* sm, long baseRow, int b, int tyk, int cg) {
    constexpr int NT = (N + 31) / 32;
    uint32_t sb = smem_to_u32(sm);
    int t = threadIdx.x, lane = t & 31, wid = t >> 5;
    int ti = tyk / NT, tk = tyk % NT;
    int i0 = ti * 32, k0 = tk * 32;
    long blk = baseRow + (long)b * (N * N);
    const float* m1p = g_m1 + blk * 64;
    const float* m2p = g_m2 + blk * 64;

    int sr = t & 31, sch = t >> 5;             // staging: row, channel
    long chbase = (long)(cg * 8 + sch) * (N * N);
    uint32_t rowoff = (uint32_t)((sr >> 1) * 128 + (sr & 1) * 64);
    uint32_t sA = (uint32_t)(sch * 2048);
    const int nk = (k0 + 32 <= N) ? 32 : (N - k0);

    float acc[2][4][4];
#pragma unroll
    for (int m = 0; m < 2; m++)
#pragma unroll
        for (int n8 = 0; n8 < 4; n8++)
#pragma unroll
            for (int q = 0; q < 4; q++) acc[m][n8][q] = 0.f;

    const bool iok = (i0 + sr < N);
    const long arow = chbase + (long)(i0 + sr) * N;

#pragma unroll
    for (int jc = 0; jc < NT; jc++) {
        const int j0 = jc * 32;
        const int nj = (j0 + 32 <= N) ? 32 : (N - j0);
        __syncthreads();
        // ---- stage A (i-rows, j-window): fp32 -> split -> bf16 hi/lo ----
        {
            float4 f[8];
#pragma unroll
            for (int q = 0; q < 8; q++) f[q] = make_float4(0.f, 0.f, 0.f, 0.f);
            if (iok) {
                const float* p = m1p + arow + j0;
#pragma unroll
                for (int q = 0; q < 8; q++)
                    if (q * 4 < nj) f[q] = ld4(p + q * 4);
            }
            uint32_t h[16], l[16];
#pragma unroll
            for (int q = 0; q < 8; q++) {
                split2(f[q].x, f[q].y, h[2 * q], l[2 * q]);
                split2(f[q].z, f[q].w, h[2 * q + 1], l[2 * q + 1]);
            }
#pragma unroll
            for (int g = 0; g < 4; g++) {
                uint32_t off = sA + swz(rowoff + g * 16);
                *reinterpret_cast<uint4*>(sm + BAH + off) =
                    make_uint4(h[4 * g], h[4 * g + 1], h[4 * g + 2], h[4 * g + 3]);
                *reinterpret_cast<uint4*>(sm + BAL + off) =
                    make_uint4(l[4 * g], l[4 * g + 1], l[4 * g + 2], l[4 * g + 3]);
            }
        }
        // ---- stage B (j-rows, k-window) ----
        {
            float4 f[8];
#pragma unroll
            for (int q = 0; q < 8; q++) f[q] = make_float4(0.f, 0.f, 0.f, 0.f);
            if (j0 + sr < N) {
                const float* p = m2p + chbase + (long)(j0 + sr) * N + k0;
#pragma unroll
                for (int q = 0; q < 8; q++)
                    if (q * 4 < nk) f[q] = ld4(p + q * 4);
            }
            uint32_t h[16], l[16];
#pragma unroll
            for (int q = 0; q < 8; q++) {
                split2(f[q].x, f[q].y, h[2 * q], l[2 * q]);
                split2(f[q].z, f[q].w, h[2 * q + 1], l[2 * q + 1]);
            }
#pragma unroll
            for (int g = 0; g < 4; g++) {
                uint32_t off = sA + swz(rowoff + g * 16);
                *reinterpret_cast<uint4*>(sm + BBH + off) =
                    make_uint4(h[4 * g], h[4 * g + 1], h[4 * g + 2], h[4 * g + 3]);
                *reinterpret_cast<uint4*>(sm + BBL + off) =
                    make_uint4(l[4 * g], l[4 * g + 1], l[4 * g + 2], l[4 * g + 3]);
            }
        }
        __syncthreads();
        // ---- MMA: warp wid computes channel wid's 32x32 tile over K=32 ----
        {
            uint32_t aH = sb + BAH + wid * 2048, aL = sb + BAL + wid * 2048;
            uint32_t bH = sb + BBH + wid * 2048, bL = sb + BBL + wid * 2048;
#pragma unroll
            for (int ks = 0; ks < 2; ks++) {
                uint32_t ah[2][4], al[2][4];
#pragma unroll
                for (int m = 0; m < 2; m++) {
                    int ri = m * 16 + (lane & 15);
                    uint32_t offA = swz((uint32_t)((ri >> 1) * 128 + (ri & 1) * 64 +
                                                   (ks * 2 + (lane >> 4)) * 16));
                    ldsm_x4(ah[m], aH + offA);
                    ldsm_x4(al[m], aL + offA);
                }
#pragma unroll
                for (int nb = 0; nb < 2; nb++) {
                    int jr = ks * 16 + (lane & 15);
                    uint32_t offB = swz((uint32_t)((jr >> 1) * 128 + (jr & 1) * 64 +
                                                   (nb * 2 + (lane >> 4)) * 16));
                    uint32_t bh[4], bl[4];
                    ldsm_x4_t(bh, bH + offB);
                    ldsm_x4_t(bl, bL + offB);
#pragma unroll
                    for (int m = 0; m < 2; m++) {
                        mma16816(acc[m][nb * 2 + 0], ah[m], &bh[0]);
                        mma16816(acc[m][nb * 2 + 0], al[m], &bh[0]);
                        mma16816(acc[m][nb * 2 + 0], ah[m], &bl[0]);
                        mma16816(acc[m][nb * 2 + 1], ah[m], &bh[2]);
                        mma16816(acc[m][nb * 2 + 1], al[m], &bh[2]);
                        mma16816(acc[m][nb * 2 + 1], ah[m], &bl[2]);
                    }
                }
            }
        }
    }
    __syncthreads();
    // ---- stage C tiles (fp32) into smem: Cs[ch][i][k], stride 33 ----
    float* Cs = reinterpret_cast<float*>(sm);
    {
        int g = lane >> 2, cbl = (lane & 3) * 2;
#pragma unroll
        for (int m = 0; m < 2; m++)
#pragma unroll
            for (int n8 = 0; n8 < 4; n8++)
#pragma unroll
                for (int rs = 0; rs < 2; rs++) {
                    int r = m * 16 + rs * 8 + g;
                    Cs[wid * 1056 + r * 33 + n8 * 8 + cbl + 0] = acc[m][n8][rs * 2 + 0];
                    Cs[wid * 1056 + r * 33 + n8 * 8 + cbl + 1] = acc[m][n8][rs * 2 + 1];
                }
    }
    __syncthreads();
    // ---- PURE coalesced store into g_hs2 (no RMW): 8 ch = 32B sector ----
#pragma unroll
    for (int it = 0; it < 4; it++) {
        int ik = it * 256 + t;
        int i = ik >> 5, k = ik & 31;
        if (i0 + i < N && k0 + k < N) {
            float* p = g_hs2 + (blk + (long)(i0 + i) * N + (k0 + k)) * 64 + cg * 8;
            float v[8];
#pragma unroll
            for (int ch = 0; ch < 8; ch++) v[ch] = Cs[ch * 1056 + i * 33 + k];
            st4(p, make_float4(v[0], v[1], v[2], v[3]));
            st4(p + 4, make_float4(v[4], v[5], v[6], v[7]));
        }
    }
}

// Fused dispatcher. CTA layout (longest variant first to avoid tail):
//   [0,    1152): N=96, 16 blocks x 9 tyk x 8 cg, baseRow 409600
//   [1152, 2176): N=64, 32 blocks x 4 tyk x 8 cg, baseRow 278528
//   [2176, 4224): N=48, 64 blocks x 4 tyk x 8 cg, baseRow 131072
//   [4224, 5248): N=32, 128 blocks x 1 tyk x 8 cg, baseRow 0
__global__ void __launch_bounds__(256) kernelBall() {
    extern __shared__ char sm[];
    int bx = blockIdx.x;
    if (bx < 1152) {
        int local = bx;
        int b = local % 16, tyk = (local / 16) % 9, cg = local / 144;
        runB<96>(sm, 409600L, b, tyk, cg);
    } else if (bx < 2176) {
        int local = bx - 1152;
        int b = local % 32, tyk = (local / 32) % 4, cg = local / 128;
        runB<64>(sm, 278528L, b, tyk, cg);
    } else if (bx < 4224) {
        int local = bx - 2176;
        int b = local % 64, tyk = (local / 64) % 4, cg = local / 256;
        runB<48>(sm, 131072L, b, tyk, cg);
    } else {
        int local = bx - 4224;
        int b = local % 128, tyk = 0, cg = local / 128;
        runB<32>(sm, 0L, b, tyk, cg);
    }
}

// ==== Kernel C: hs2 = h + x@Wskip+b; Lin+BN+ReLU x2; out = u + hs2 =========
__global__ void __launch_bounds__(128) kernelC(
    const float* __restrict__ x, const float* __restrict__ b_skip,
    const float* __restrict__ b_u1, const float* __restrict__ g1,
    const float* __restrict__ beta1, const float* __restrict__ rm1,
    const float* __restrict__ rv1,
    const float* __restrict__ b_u2, const float* __restrict__ g2,
    const float* __restrict__ beta2, const float* __restrict__ rm2,
    const float* __restrict__ rv2,
    float* __restrict__ out) {
    extern __shared__ char sm[];
    uint32_t sb = smem_to_u32(sm);
    int tid = threadIdx.x, wid = tid >> 5, lane = tid & 31;
    long row0 = (long)blockIdx.x * 128;
    float* par = reinterpret_cast<float*>(sm + OPAR);

    if (tid < 64) {
        par[tid] = b_u1[tid];
        float sc1 = g1[tid] * rsqrtf(rv1[tid] + 1e-5f);
        par[64 + tid] = sc1;
        par[128 + tid] = beta1[tid] - rm1[tid] * sc1;
        par[192 + tid] = b_u2[tid];
        float sc2 = g2[tid] * rsqrtf(rv2[tid] + 1e-5f);
        par[256 + tid] = sc2;
        par[320 + tid] = beta2[tid] - rm2[tid] * sc2;
        par[384 + tid] = b_skip[tid];
    }
    convertX(sm, x + row0 * 64, tid);
    copyW(sm, 4, tid);   // W_skip
    __syncthreads();

    float acc[2][8][4];

    // GEMM0: x @ W_skip -> acc; then hs2 = acc + b_skip + h (fragment loads)
    warp_gemm(sb, OXH, OXL, acc, wid, lane);
    {
        int g = lane >> 2;
#pragma unroll
        for (int m = 0; m < 2; m++)
#pragma unroll
            for (int rs = 0; rs < 2; rs++) {
                long row = row0 + wid * 32 + m * 16 + rs * 8 + g;
#pragma unroll
                for (int nt = 0; nt < 8; nt++) {
                    int c = nt * 8 + (lane & 3) * 2;
                    float2 hv = *reinterpret_cast<const float2*>(g_hs2 + row * 64 + c);
                    acc[m][nt][rs * 2 + 0] += par[384 + c] + hv.x;
                    acc[m][nt][rs * 2 + 1] += par[384 + c + 1] + hv.y;
                }
            }
    }
    __syncthreads();   // all warps done reading X tiles before overwrite
    // store hs2 (no relu) into OXH/OXL as split bf16 (GEMM1 input + residual)
    {
        int g = lane >> 2, cb = (lane & 3) * 4;
#pragma unroll
        for (int m = 0; m < 2; m++)
#pragma unroll
            for (int rs = 0; rs < 2; rs++) {
                int row = wid * 32 + m * 16 + rs * 8 + g;
#pragma unroll
                for (int nt = 0; nt < 8; nt++) {
                    uint32_t h, l;
                    split2(acc[m][nt][rs * 2 + 0], acc[m][nt][rs * 2 + 1], h, l);
                    uint32_t off = swz((uint32_t)(row * 128 + nt * 16 + cb));
                    *reinterpret_cast<uint32_t*>(sm + OXH + off) = h;
                    *reinterpret_cast<uint32_t*>(sm + OXL + off) = l;
                }
            }
    }
    copyW(sm, 5, tid);   // W_u1
    __syncthreads();

    // GEMM1: hs2 @ W_u1 -> H = relu(bn1(. + b_u1))
    warp_gemm(sb, OXH, OXL, acc, wid, lane);
    __syncthreads();
    {
        int g = lane >> 2, cb = (lane & 3) * 4;
#pragma unroll
        for (int m = 0; m < 2; m++)
#pragma unroll
            for (int rs = 0; rs < 2; rs++) {
                int row = wid * 32 + m * 16 + rs * 8 + g;
#pragma unroll
                for (int nt = 0; nt < 8; nt++) {
                    int c = nt * 8 + (lane & 3) * 2;
                    float v0 = fmaxf((acc[m][nt][rs * 2 + 0] + par[c]) * par[64 + c] + par[128 + c], 0.f);
                    float v1 = fmaxf((acc[m][nt][rs * 2 + 1] + par[c + 1]) * par[64 + c + 1] + par[128 + c + 1], 0.f);
                    uint32_t h, l;
                    split2(v0, v1, h, l);
                    uint32_t off = swz((uint32_t)(row * 128 + nt * 16 + cb));
                    *reinterpret_cast<uint32_t*>(sm + OHH + off) = h;
                    *reinterpret_cast<uint32_t*>(sm + OHL + off) = l;
                }
            }
    }
    copyW(sm, 6, tid);   // W_u2
    __syncthreads();

    // GEMM2: H @ W_u2 -> out = relu(bn2(. + b_u2)) + hs2
    warp_gemm(sb, OHH, OHL, acc, wid, lane);
    {
        int g = lane >> 2, cb = (lane & 3) * 4;
#pragma unroll
        for (int m = 0; m < 2; m++)
#pragma unroll
            for (int rs = 0; rs < 2; rs++) {
                int row = wid * 32 + m * 16 + rs * 8 + g;
                long grow = row0 + row;
#pragma unroll
                for (int nt = 0; nt < 8; nt++) {
                    int c = nt * 8 + (lane & 3) * 2;
                    float u0 = fmaxf((acc[m][nt][rs * 2 + 0] + par[192 + c]) * par[256 + c] + par[320 + c], 0.f);
                    float u1 = fmaxf((acc[m][nt][rs * 2 + 1] + par[192 + c + 1]) * par[256 + c + 1] + par[320 + c + 1], 0.f);
                    uint32_t off = swz((uint32_t)(row * 128 + nt * 16 + cb));
                    uint32_t xh = *reinterpret_cast<uint32_t*>(sm + OXH + off);
                    uint32_t xl = *reinterpret_cast<uint32_t*>(sm + OXL + off);
                    float2 h2 = __bfloat1622float2(*reinterpret_cast<__nv_bfloat162*>(&xh));
                    float2 l2 = __bfloat1622float2(*reinterpret_cast<__nv_bfloat162*>(&xl));
                    *reinterpret_cast<float2*>(out + grow * 64 + c) =
                        make_float2(u0 + (h2.x + l2.x), u1 + (h2.y + l2.y));
                }
            }
    }
}

// ---------------------------------------------------------------------------
extern "C" void kernel_launch(void* const* d_in, const int* in_sizes, int n_in,
                              void* d_out, int out_size) {
    (void)in_sizes; (void)n_in; (void)out_size;
    const float* x      = (const float*)d_in[0];
    const float* w_m1   = (const float*)d_in[1];
    const float* b_m1   = (const float*)d_in[2];
    const float* w_m2   = (const float*)d_in[3];
    const float* b_m2   = (const float*)d_in[4];
    const float* W_skip = (const float*)d_in[5];
    const float* b_skip = (const float*)d_in[6];
    const float* W_u1   = (const float*)d_in[7];
    const float* b_u1   = (const float*)d_in[8];
    const float* g1     = (const float*)d_in[9];
    const float* beta1  = (const float*)d_in[10];
    const float* rm1    = (const float*)d_in[11];
    const float* rv1    = (const float*)d_in[12];
    const float* W_u2   = (const float*)d_in[13];
    const float* b_u2   = (const float*)d_in[14];
    const float* g2     = (const float*)d_in[15];
    const float* beta2  = (const float*)d_in[16];
    const float* rm2    = (const float*)d_in[17];
    const float* rv2    = (const float*)d_in[18];
    float* out = (float*)d_out;

    cudaFuncSetAttribute(kernelA, cudaFuncAttributeMaxDynamicSharedMemorySize, SMEM_BYTES);
    cudaFuncSetAttribute(kernelC, cudaFuncAttributeMaxDynamicSharedMemorySize, SMEM_BYTES);
    cudaFuncSetAttribute(kernelBall, cudaFuncAttributeMaxDynamicSharedMemorySize, 65536);

    kernelW<<<dim3(16, 7), 256>>>(w_m1, w_m2, W_skip, W_u1, W_u2);

    kernelA<<<N_TOTAL / 128, 128, SMEM_BYTES>>>(x, b_m1, b_m2);

    // fused kernelB: all 4 block-size variants, longest first (5248 CTAs)
    kernelBall<<<5248, 256, 65536>>>();

    kernelC<<<N_TOTAL / 128, 128, SMEM_BYTES>>>(x, b_skip, b_u1, g1, beta1, rm1, rv1,
                                                b_u2, g2, beta2, rm2, rv2, out);
}

// round 14
// speedup vs baseline: 1.0620x; 1.0095x over previous
#include <cuda_runtime.h>
#include <cuda_bf16.h>
#include <cstdint>

#define N_TOTAL 557056
#define NC 64

// Scratch (device globals — no allocation allowed)
// g_m1/g_m2: MLP outputs TRANSPOSED per graph-block (c, i*n+j), fp32
__device__ float g_m1[N_TOTAL * NC];
__device__ float g_m2[N_TOTAL * NC];
__device__ float g_hs2[N_TOTAL * NC];   // holds h (spatial matmul result) only
// Pre-split, pre-swizzled weights: 7 matrices x 4096 bf16 (hi and lo), SW128 layout
__device__ uint4 g_wh4[7 * 512];
__device__ uint4 g_wl4[7 * 512];

__device__ __forceinline__ float4 ld4(const float* p) { return *reinterpret_cast<const float4*>(p); }
__device__ __forceinline__ void st4(float* p, float4 v) { *reinterpret_cast<float4*>(p) = v; }

__device__ __forceinline__ uint32_t smem_to_u32(const void* smem_ptr) {
    uint32_t addr;
    asm("{ .reg .u64 tmp; cvta.to.shared.u64 tmp, %1; cvt.u32.u64 %0, tmp; }"
        : "=r"(addr) : "l"(smem_ptr));
    return addr;
}
__device__ __forceinline__ uint32_t swz(uint32_t off) { return off ^ ((off >> 3) & 0x70); }

// ===================== cp.async (LDGSTS) helpers ===========================
__device__ __forceinline__ void cpasync16(uint32_t dst, const void* src) {
    asm volatile("cp.async.cg.shared.global [%0], [%1], 16;"
                 :: "r"(dst), "l"(src) : "memory");
}
__device__ __forceinline__ void cp_commit() {
    asm volatile("cp.async.commit_group;" ::: "memory");
}
__device__ __forceinline__ void cp_wait0() {
    asm volatile("cp.async.wait_group 0;" ::: "memory");
}

// ===================== mma.sync / ldmatrix machinery =======================
__device__ __forceinline__ void ldsm_x4(uint32_t r[4], uint32_t addr) {
    asm volatile("ldmatrix.sync.aligned.m8n8.x4.shared.b16 {%0,%1,%2,%3}, [%4];"
                 : "=r"(r[0]), "=r"(r[1]), "=r"(r[2]), "=r"(r[3]) : "r"(addr));
}
__device__ __forceinline__ void ldsm_x4_t(uint32_t r[4], uint32_t addr) {
    asm volatile("ldmatrix.sync.aligned.m8n8.x4.trans.shared.b16 {%0,%1,%2,%3}, [%4];"
                 : "=r"(r[0]), "=r"(r[1]), "=r"(r[2]), "=r"(r[3]) : "r"(addr));
}
__device__ __forceinline__ void mma16816(float c[4], const uint32_t a[4], const uint32_t b[2]) {
    asm volatile("mma.sync.aligned.m16n8k16.row.col.f32.bf16.bf16.f32 "
                 "{%0,%1,%2,%3}, {%4,%5,%6,%7}, {%8,%9}, {%0,%1,%2,%3};"
                 : "+f"(c[0]), "+f"(c[1]), "+f"(c[2]), "+f"(c[3])
                 : "r"(a[0]), "r"(a[1]), "r"(a[2]), "r"(a[3]), "r"(b[0]), "r"(b[1]));
}

// bf16 two-term split of a float pair
__device__ __forceinline__ void split2(float a, float b, uint32_t& h, uint32_t& l) {
    __nv_bfloat162 hh = __floats2bfloat162_rn(a, b);
    float la = a - __bfloat162float(hh.x);
    float lb = b - __bfloat162float(hh.y);
    __nv_bfloat162 ll = __floats2bfloat162_rn(la, lb);
    h = *reinterpret_cast<uint32_t*>(&hh);
    l = *reinterpret_cast<uint32_t*>(&ll);
}

// ===================== SMEM layout for kernels A and C =====================
#define OXH 0
#define OXL 16384
#define OHH 32768
#define OHL 49152
#define OBH 65536
#define OBL 73728
#define OPAR 81920
#define SMEM_BYTES 83968

// load B fragments (8 n-tiles) for one k16 step from a 64x64 bf16 SW128 tile
__device__ __forceinline__ void loadB(uint32_t bf[16], uint32_t sbW, int ks, int lane) {
    int rowB = (lane & 7) + ((lane >> 4) << 3);
    int chB = ks * 2 + ((lane >> 3) & 1);
#pragma unroll
    for (int t = 0; t < 4; t++) {
        uint32_t off = swz((uint32_t)((t * 16 + rowB) * 128 + chB * 16));
        ldsm_x4(bf + 4 * t, sbW + off);
    }
}

// warp GEMM: rows [wid*32, wid*32+32) x 64 cols, K=64, 3-term bf16 split
__device__ __forceinline__ void warp_gemm(uint32_t sb, int aHi, int aLo,
                                          float acc[2][8][4], int wid, int lane) {
#pragma unroll
    for (int m = 0; m < 2; m++)
#pragma unroll
        for (int nt = 0; nt < 8; nt++)
#pragma unroll
            for (int q = 0; q < 4; q++) acc[m][nt][q] = 0.f;

#pragma unroll
    for (int ks = 0; ks < 4; ks++) {
        uint32_t ah[2][4], al[2][4], bf[16];
        int rowA = wid * 32 + (lane & 15);
        int chA = ks * 2 + (lane >> 4);
        uint32_t offA0 = swz((uint32_t)(rowA * 128 + chA * 16));
        uint32_t offA1 = swz((uint32_t)((rowA + 16) * 128 + chA * 16));
        ldsm_x4(ah[0], sb + aHi + offA0);
        ldsm_x4(ah[1], sb + aHi + offA1);
        ldsm_x4(al[0], sb + aLo + offA0);
        ldsm_x4(al[1], sb + aLo + offA1);
        loadB(bf, sb + OBH, ks, lane);
#pragma unroll
        for (int m = 0; m < 2; m++)
#pragma unroll
            for (int p = 0; p < 4; p++) {
                mma16816(acc[m][2 * p], ah[m], &bf[4 * p]);
                mma16816(acc[m][2 * p], al[m], &bf[4 * p]);
                mma16816(acc[m][2 * p + 1], ah[m], &bf[4 * p + 2]);
                mma16816(acc[m][2 * p + 1], al[m], &bf[4 * p + 2]);
            }
        loadB(bf, sb + OBL, ks, lane);
#pragma unroll
        for (int m = 0; m < 2; m++)
#pragma unroll
            for (int p = 0; p < 4; p++) {
                mma16816(acc[m][2 * p], ah[m], &bf[4 * p]);
                mma16816(acc[m][2 * p + 1], ah[m], &bf[4 * p + 2]);
            }
    }
}

// copy pre-swizzled weight matrix m into OBH/OBL (8KB each)
__device__ __forceinline__ void copyW(char* sm, int m, int tid) {
#pragma unroll
    for (int i = 0; i < 4; i++) {
        int idx = i * 128 + tid;
        reinterpret_cast<uint4*>(sm + OBH)[idx] = g_wh4[m * 512 + idx];
        reinterpret_cast<uint4*>(sm + OBL)[idx] = g_wl4[m * 512 + idx];
    }
}

// convert 128 rows x 64 fp32 (row-major gmem) -> bf16 hi/lo SW128 smem tiles
__device__ __forceinline__ void convertX(char* sm, const float* __restrict__ src, int tid) {
#pragma unroll
    for (int i = 0; i < 8; i++) {
        int idx = i * 128 + tid;
        int r = idx >> 3, g = idx & 7;
        const float* p = src + r * 64 + g * 8;
        float4 f0 = ld4(p), f1 = ld4(p + 4);
        float vv[8] = {f0.x, f0.y, f0.z, f0.w, f1.x, f1.y, f1.z, f1.w};
        uint32_t hw[4], lw[4];
#pragma unroll
        for (int q = 0; q < 4; q++) split2(vv[2 * q], vv[2 * q + 1], hw[q], lw[q]);
        uint32_t off = swz((uint32_t)(r * 128 + g * 16));
        *reinterpret_cast<uint4*>(sm + OXH + off) = make_uint4(hw[0], hw[1], hw[2], hw[3]);
        *reinterpret_cast<uint4*>(sm + OXL + off) = make_uint4(lw[0], lw[1], lw[2], lw[3]);
    }
}

// ========================== setup: split weights ===========================
__global__ void kernelW(const float* __restrict__ w_m1, const float* __restrict__ w_m2,
                        const float* __restrict__ W_skip, const float* __restrict__ W_u1,
                        const float* __restrict__ W_u2) {
    int m = blockIdx.y;
    int idx = blockIdx.x * 256 + threadIdx.x;
    const float* W;
    switch (m) {
        case 0: W = w_m1; break;
        case 1: W = w_m1 + 4096; break;
        case 2: W = w_m2; break;
        case 3: W = w_m2 + 4096; break;
        case 4: W = W_skip; break;
        case 5: W = W_u1; break;
        default: W = W_u2; break;
    }
    float v = W[idx];
    int o = idx >> 6, k = idx & 63;
    __nv_bfloat16 h = __float2bfloat16(v);
    __nv_bfloat16 l = __float2bfloat16(v - __bfloat162float(h));
    uint32_t eoff = swz((uint32_t)(o * 128 + k * 2)) >> 1;
    reinterpret_cast<__nv_bfloat16*>(g_wh4)[m * 4096 + eoff] = h;
    reinterpret_cast<__nv_bfloat16*>(g_wl4)[m * 4096 + eoff] = l;
}

// ======= epilogue helpers =========
// store acc (+bias, relu) as split bf16 into HH/HL
__device__ __forceinline__ void epiH(char* sm, const float acc[2][8][4], const float* bias,
                                     int wid, int lane) {
    int g = lane >> 2, cb = (lane & 3) * 4;
#pragma unroll
    for (int m = 0; m < 2; m++)
#pragma unroll
        for (int rs = 0; rs < 2; rs++) {
            int row = wid * 32 + m * 16 + rs * 8 + g;
#pragma unroll
            for (int nt = 0; nt < 8; nt++) {
                int c = nt * 8 + (lane & 3) * 2;
                float v0 = fmaxf(acc[m][nt][rs * 2 + 0] + bias[c], 0.f);
                float v1 = fmaxf(acc[m][nt][rs * 2 + 1] + bias[c + 1], 0.f);
                uint32_t h, l;
                split2(v0, v1, h, l);
                uint32_t off = swz((uint32_t)(row * 128 + nt * 16 + cb));
                *reinterpret_cast<uint32_t*>(sm + OHH + off) = h;
                *reinterpret_cast<uint32_t*>(sm + OHL + off) = l;
            }
        }
}

// store acc (+bias, relu) TRANSPOSED per-block: dst[(c)*nsq + localRow], fp32
__device__ __forceinline__ void epiT(float* __restrict__ dst, int nsq, long localRow0,
                                     const float acc[2][8][4], const float* bias,
                                     int wid, int lane) {
    int g = lane >> 2;
#pragma unroll
    for (int m = 0; m < 2; m++)
#pragma unroll
        for (int rs = 0; rs < 2; rs++) {
            long rl = localRow0 + wid * 32 + m * 16 + rs * 8 + g;
#pragma unroll
            for (int nt = 0; nt < 8; nt++) {
                int c = nt * 8 + (lane & 3) * 2;
                dst[(long)c * nsq + rl] = fmaxf(acc[m][nt][rs * 2 + 0] + bias[c], 0.f);
                dst[(long)(c + 1) * nsq + rl] = fmaxf(acc[m][nt][rs * 2 + 1] + bias[c + 1], 0.f);
            }
        }
}

// =============== Kernel A: x -> m1t, m2t (2-layer MLPs) ====================
__global__ void __launch_bounds__(128) kernelA(
    const float* __restrict__ x,
    const float* __restrict__ b_m1, const float* __restrict__ b_m2) {
    extern __shared__ char sm[];
    uint32_t sb = smem_to_u32(sm);
    int tid = threadIdx.x, wid = tid >> 5, lane = tid & 31;
    long row0 = (long)blockIdx.x * 128;
    float* par = reinterpret_cast<float*>(sm + OPAR);

    // bucket mapping (all 128 rows lie in one graph-block: n^2 % 128 == 0)
    int n_, nsq;
    long bbase;
    if (row0 < 131072L)      { n_ = 32; bbase = 0L; }
    else if (row0 < 278528L) { n_ = 48; bbase = 131072L; }
    else if (row0 < 409600L) { n_ = 64; bbase = 278528L; }
    else                     { n_ = 96; bbase = 409600L; }
    nsq = n_ * n_;
    long blk_start = bbase + ((row0 - bbase) / nsq) * nsq;
    long localRow0 = row0 - blk_start;
    float* d1 = g_m1 + blk_start * 64;
    float* d2 = g_m2 + blk_start * 64;

    if (tid < 64) {
        par[tid] = b_m1[tid];
        par[64 + tid] = b_m1[64 + tid];
        par[128 + tid] = b_m2[tid];
        par[192 + tid] = b_m2[64 + tid];
    }
    convertX(sm, x + row0 * 64, tid);
    copyW(sm, 0, tid);
    __syncthreads();

    float acc[2][8][4];

    // GEMM1: X @ Wm1_0 -> H (relu)
    warp_gemm(sb, OXH, OXL, acc, wid, lane);
    __syncthreads();
    epiH(sm, acc, par, wid, lane);
    copyW(sm, 1, tid);
    __syncthreads();

    // GEMM2: H @ Wm1_1 -> g_m1 transposed (relu)
    warp_gemm(sb, OHH, OHL, acc, wid, lane);
    __syncthreads();
    epiT(d1, nsq, localRow0, acc, par + 64, wid, lane);
    copyW(sm, 2, tid);
    __syncthreads();

    // GEMM3: X @ Wm2_0 -> H (relu)
    warp_gemm(sb, OXH, OXL, acc, wid, lane);
    __syncthreads();
    epiH(sm, acc, par + 128, wid, lane);
    copyW(sm, 3, tid);
    __syncthreads();

    // GEMM4: H @ Wm2_1 -> g_m2 transposed (relu)
    warp_gemm(sb, OHH, OHL, acc, wid, lane);
    __syncthreads();
    epiT(d2, nsq, localRow0, acc, par + 192, wid, lane);
}

// ---------------------------------------------------------------------------
// Kernel B (tensor-core, FUSED single launch): per-block spatial matmul
//   h[b,i,k,c] = sum_j m1[b,i,j,c]*m2[b,j,k,c];  g_hs2 = h (PURE STORE)
// CTA = (block b, 32x32 i/k tile, 8 channels). Warp w owns channel w.
// ---------------------------------------------------------------------------
#define BAH 0
#define BAL 16384
#define BBH 32768
#define BBL 49152

template <int N>
__device__ __forceinline__ void runB(char* sm, long baseRow, int b, int tyk, int cg) {
    constexpr int NT = (N + 31) / 32;
    uint32_t sb = smem_to_u32(sm);
    int t = threadIdx.x, lane = t & 31, wid = t >> 5;
    int ti = tyk / NT, tk = tyk % NT;
    int i0 = ti * 32, k0 = tk * 32;
    long blk = baseRow + (long)b * (N * N);
    const float* m1p = g_m1 + blk * 64;
    const float* m2p = g_m2 + blk * 64;

    int sr = t & 31, sch = t >> 5;             // staging: row, channel
    long chbase = (long)(cg * 8 + sch) * (N * N);
    uint32_t rowoff = (uint32_t)((sr >> 1) * 128 + (sr & 1) * 64);
    uint32_t sA = (uint32_t)(sch * 2048);
    const int nk = (k0 + 32 <= N) ? 32 : (N - k0);

    float acc[2][4][4];
#pragma unroll
    for (int m = 0; m < 2; m++)
#pragma unroll
        for (int n8 = 0; n8 < 4; n8++)
#pragma unroll
            for (int q = 0; q < 4; q++) acc[m][n8][q] = 0.f;

    const bool iok = (i0 + sr < N);
    const long arow = chbase + (long)(i0 + sr) * N;

#pragma unroll
    for (int jc = 0; jc < NT; jc++) {
        const int j0 = jc * 32;
        const int nj = (j0 + 32 <= N) ? 32 : (N - j0);
        __syncthreads();
        // ---- stage A (i-rows, j-window): fp32 -> split -> bf16 hi/lo ----
        {
            float4 f[8];
#pragma unroll
            for (int q = 0; q < 8; q++) f[q] = make_float4(0.f, 0.f, 0.f, 0.f);
            if (iok) {
                const float* p = m1p + arow + j0;
#pragma unroll
                for (int q = 0; q < 8; q++)
                    if (q * 4 < nj) f[q] = ld4(p + q * 4);
            }
            uint32_t h[16], l[16];
#pragma unroll
            for (int q = 0; q < 8; q++) {
                split2(f[q].x, f[q].y, h[2 * q], l[2 * q]);
                split2(f[q].z, f[q].w, h[2 * q + 1], l[2 * q + 1]);
            }
#pragma unroll
            for (int g = 0; g < 4; g++) {
                uint32_t off = sA + swz(rowoff + g * 16);
                *reinterpret_cast<uint4*>(sm + BAH + off) =
                    make_uint4(h[4 * g], h[4 * g + 1], h[4 * g + 2], h[4 * g + 3]);
                *reinterpret_cast<uint4*>(sm + BAL + off) =
                    make_uint4(l[4 * g], l[4 * g + 1], l[4 * g + 2], l[4 * g + 3]);
            }
        }
        // ---- stage B (j-rows, k-window) ----
        {
            float4 f[8];
#pragma unroll
            for (int q = 0; q < 8; q++) f[q] = make_float4(0.f, 0.f, 0.f, 0.f);
            if (j0 + sr < N) {
                const float* p = m2p + chbase + (long)(j0 + sr) * N + k0;
#pragma unroll
                for (int q = 0; q < 8; q++)
                    if (q * 4 < nk) f[q] = ld4(p + q * 4);
            }
            uint32_t h[16], l[16];
#pragma unroll
            for (int q = 0; q < 8; q++) {
                split2(f[q].x, f[q].y, h[2 * q], l[2 * q]);
                split2(f[q].z, f[q].w, h[2 * q + 1], l[2 * q + 1]);
            }
#pragma unroll
            for (int g = 0; g < 4; g++) {
                uint32_t off = sA + swz(rowoff + g * 16);
                *reinterpret_cast<uint4*>(sm + BBH + off) =
                    make_uint4(h[4 * g], h[4 * g + 1], h[4 * g + 2], h[4 * g + 3]);
                *reinterpret_cast<uint4*>(sm + BBL + off) =
                    make_uint4(l[4 * g], l[4 * g + 1], l[4 * g + 2], l[4 * g + 3]);
            }
        }
        __syncthreads();
        // ---- MMA: warp wid computes channel wid's 32x32 tile over K=32 ----
        {
            uint32_t aH = sb + BAH + wid * 2048, aL = sb + BAL + wid * 2048;
            uint32_t bH = sb + BBH + wid * 2048, bL = sb + BBL + wid * 2048;
#pragma unroll
            for (int ks = 0; ks < 2; ks++) {
                uint32_t ah[2][4], al[2][4];
#pragma unroll
                for (int m = 0; m < 2; m++) {
                    int ri = m * 16 + (lane & 15);
                    uint32_t offA = swz((uint32_t)((ri >> 1) * 128 + (ri & 1) * 64 +
                                                   (ks * 2 + (lane >> 4)) * 16));
                    ldsm_x4(ah[m], aH + offA);
                    ldsm_x4(al[m], aL + offA);
                }
#pragma unroll
                for (int nb = 0; nb < 2; nb++) {
                    int jr = ks * 16 + (lane & 15);
                    uint32_t offB = swz((uint32_t)((jr >> 1) * 128 + (jr & 1) * 64 +
                                                   (nb * 2 + (lane >> 4)) * 16));
                    uint32_t bh[4], bl[4];
                    ldsm_x4_t(bh, bH + offB);
                    ldsm_x4_t(bl, bL + offB);
#pragma unroll
                    for (int m = 0; m < 2; m++) {
                        mma16816(acc[m][nb * 2 + 0], ah[m], &bh[0]);
                        mma16816(acc[m][nb * 2 + 0], al[m], &bh[0]);
                        mma16816(acc[m][nb * 2 + 0], ah[m], &bl[0]);
                        mma16816(acc[m][nb * 2 + 1], ah[m], &bh[2]);
                        mma16816(acc[m][nb * 2 + 1], al[m], &bh[2]);
                        mma16816(acc[m][nb * 2 + 1], ah[m], &bl[2]);
                    }
                }
            }
        }
    }
    __syncthreads();
    // ---- stage C tiles (fp32) into smem: Cs[ch][i][k], stride 33 ----
    float* Cs = reinterpret_cast<float*>(sm);
    {
        int g = lane >> 2, cbl = (lane & 3) * 2;
#pragma unroll
        for (int m = 0; m < 2; m++)
#pragma unroll
            for (int n8 = 0; n8 < 4; n8++)
#pragma unroll
                for (int rs = 0; rs < 2; rs++) {
                    int r = m * 16 + rs * 8 + g;
                    Cs[wid * 1056 + r * 33 + n8 * 8 + cbl + 0] = acc[m][n8][rs * 2 + 0];
                    Cs[wid * 1056 + r * 33 + n8 * 8 + cbl + 1] = acc[m][n8][rs * 2 + 1];
                }
    }
    __syncthreads();
    // ---- PURE coalesced store into g_hs2 (no RMW): 8 ch = 32B sector ----
#pragma unroll
    for (int it = 0; it < 4; it++) {
        int ik = it * 256 + t;
        int i = ik >> 5, k = ik & 31;
        if (i0 + i < N && k0 + k < N) {
            float* p = g_hs2 + (blk + (long)(i0 + i) * N + (k0 + k)) * 64 + cg * 8;
            float v[8];
#pragma unroll
            for (int ch = 0; ch < 8; ch++) v[ch] = Cs[ch * 1056 + i * 33 + k];
            st4(p, make_float4(v[0], v[1], v[2], v[3]));
            st4(p + 4, make_float4(v[4], v[5], v[6], v[7]));
        }
    }
}

// Fused dispatcher. CTA layout (longest variant first to avoid tail):
__global__ void __launch_bounds__(256) kernelBall() {
    extern __shared__ char sm[];
    int bx = blockIdx.x;
    if (bx < 1152) {
        int local = bx;
        int b = local % 16, tyk = (local / 16) % 9, cg = local / 144;
        runB<96>(sm, 409600L, b, tyk, cg);
    } else if (bx < 2176) {
        int local = bx - 1152;
        int b = local % 32, tyk = (local / 32) % 4, cg = local / 128;
        runB<64>(sm, 278528L, b, tyk, cg);
    } else if (bx < 4224) {
        int local = bx - 2176;
        int b = local % 64, tyk = (local / 64) % 4, cg = local / 256;
        runB<48>(sm, 131072L, b, tyk, cg);
    } else {
        int local = bx - 4224;
        int b = local % 128, tyk = 0, cg = local / 128;
        runB<32>(sm, 0L, b, tyk, cg);
    }
}

// ==== Kernel C: hs2 = h + x@Wskip+b; Lin+BN+ReLU x2; out = u + hs2 =========
__global__ void __launch_bounds__(128) kernelC(
    const float* __restrict__ x, const float* __restrict__ b_skip,
    const float* __restrict__ b_u1, const float* __restrict__ g1,
    const float* __restrict__ beta1, const float* __restrict__ rm1,
    const float* __restrict__ rv1,
    const float* __restrict__ b_u2, const float* __restrict__ g2,
    const float* __restrict__ beta2, const float* __restrict__ rm2,
    const float* __restrict__ rv2,
    float* __restrict__ out) {
    extern __shared__ char sm[];
    uint32_t sb = smem_to_u32(sm);
    int tid = threadIdx.x, wid = tid >> 5, lane = tid & 31;
    long row0 = (long)blockIdx.x * 128;
    float* par = reinterpret_cast<float*>(sm + OPAR);
    float* Hs2 = reinterpret_cast<float*>(sm + OHH);   // 128x64 fp32, XOR-swizzled

    // EARLY: async-stage h tile (128x64 fp32, 32KB) coalesced into OHH/OHL,
    // XOR-swizzled addr(r,c) = r*64 + (c ^ ((r&7)*8)). Overlaps with GEMM0.
#pragma unroll
    for (int i = 0; i < 16; i++) {
        int fidx = i * 128 + tid;            // float4 slot 0..2047
        int r = fidx >> 4, q = fidx & 15;
        uint32_t dst = sb + OHH + (uint32_t)(r * 64 + ((q * 4) ^ ((r & 7) * 8))) * 4;
        cpasync16(dst, g_hs2 + (row0 + r) * 64 + q * 4);
    }
    cp_commit();

    if (tid < 64) {
        par[tid] = b_u1[tid];
        float sc1 = g1[tid] * rsqrtf(rv1[tid] + 1e-5f);
        par[64 + tid] = sc1;
        par[128 + tid] = beta1[tid] - rm1[tid] * sc1;
        par[192 + tid] = b_u2[tid];
        float sc2 = g2[tid] * rsqrtf(rv2[tid] + 1e-5f);
        par[256 + tid] = sc2;
        par[320 + tid] = beta2[tid] - rm2[tid] * sc2;
        par[384 + tid] = b_skip[tid];
    }
    convertX(sm, x + row0 * 64, tid);
    copyW(sm, 4, tid);   // W_skip
    __syncthreads();

    float acc[2][8][4];

    // GEMM0: x @ W_skip -> acc (cp.async of h flies underneath)
    warp_gemm(sb, OXH, OXL, acc, wid, lane);
    cp_wait0();
    __syncthreads();
    // hs2 = acc + b_skip + h (h from smem, conflict-light swizzled reads)
    {
        int g = lane >> 2;
#pragma unroll
        for (int m = 0; m < 2; m++)
#pragma unroll
            for (int rs = 0; rs < 2; rs++) {
                int row = wid * 32 + m * 16 + rs * 8 + g;
#pragma unroll
                for (int nt = 0; nt < 8; nt++) {
                    int c = nt * 8 + (lane & 3) * 2;
                    float2 hv = *reinterpret_cast<const float2*>(
                        &Hs2[row * 64 + (c ^ ((row & 7) * 8))]);
                    acc[m][nt][rs * 2 + 0] += par[384 + c] + hv.x;
                    acc[m][nt][rs * 2 + 1] += par[384 + c + 1] + hv.y;
                }
            }
    }
    __syncthreads();   // all warps done reading X tiles + Hs2 before overwrite
    // store hs2 (no relu) into OXH/OXL as split bf16 (GEMM1 input + residual)
    {
        int g = lane >> 2, cb = (lane & 3) * 4;
#pragma unroll
        for (int m = 0; m < 2; m++)
#pragma unroll
            for (int rs = 0; rs < 2; rs++) {
                int row = wid * 32 + m * 16 + rs * 8 + g;
#pragma unroll
                for (int nt = 0; nt < 8; nt++) {
                    uint32_t h, l;
                    split2(acc[m][nt][rs * 2 + 0], acc[m][nt][rs * 2 + 1], h, l);
                    uint32_t off = swz((uint32_t)(row * 128 + nt * 16 + cb));
                    *reinterpret_cast<uint32_t*>(sm + OXH + off) = h;
                    *reinterpret_cast<uint32_t*>(sm + OXL + off) = l;
                }
            }
    }
    copyW(sm, 5, tid);   // W_u1
    __syncthreads();

    // GEMM1: hs2 @ W_u1 -> H = relu(bn1(. + b_u1))
    warp_gemm(sb, OXH, OXL, acc, wid, lane);
    __syncthreads();
    {
        int g = lane >> 2, cb = (lane & 3) * 4;
#pragma unroll
        for (int m = 0; m < 2; m++)
#pragma unroll
            for (int rs = 0; rs < 2; rs++) {
                int row = wid * 32 + m * 16 + rs * 8 + g;
#pragma unroll
                for (int nt = 0; nt < 8; nt++) {
                    int c = nt * 8 + (lane & 3) * 2;
                    float v0 = fmaxf((acc[m][nt][rs * 2 + 0] + par[c]) * par[64 + c] + par[128 + c], 0.f);
                    float v1 = fmaxf((acc[m][nt][rs * 2 + 1] + par[c + 1]) * par[64 + c + 1] + par[128 + c + 1], 0.f);
                    uint32_t h, l;
                    split2(v0, v1, h, l);
                    uint32_t off = swz((uint32_t)(row * 128 + nt * 16 + cb));
                    *reinterpret_cast<uint32_t*>(sm + OHH + off) = h;
                    *reinterpret_cast<uint32_t*>(sm + OHL + off) = l;
                }
            }
    }
    copyW(sm, 6, tid);   // W_u2
    __syncthreads();

    // GEMM2: H @ W_u2 -> out = relu(bn2(. + b_u2)) + hs2
    warp_gemm(sb, OHH, OHL, acc, wid, lane);
    {
        int g = lane >> 2, cb = (lane & 3) * 4;
#pragma unroll
        for (int m = 0; m < 2; m++)
#pragma unroll
            for (int rs = 0; rs < 2; rs++) {
                int row = wid * 32 + m * 16 + rs * 8 + g;
                long grow = row0 + row;
#pragma unroll
                for (int nt = 0; nt < 8; nt++) {
                    int c = nt * 8 + (lane & 3) * 2;
                    float u0 = fmaxf((acc[m][nt][rs * 2 + 0] + par[192 + c]) * par[256 + c] + par[320 + c], 0.f);
                    float u1 = fmaxf((acc[m][nt][rs * 2 + 1] + par[192 + c + 1]) * par[256 + c + 1] + par[320 + c + 1], 0.f);
                    uint32_t off = swz((uint32_t)(row * 128 + nt * 16 + cb));
                    uint32_t xh = *reinterpret_cast<uint32_t*>(sm + OXH + off);
                    uint32_t xl = *reinterpret_cast<uint32_t*>(sm + OXL + off);
                    float2 h2 = __bfloat1622float2(*reinterpret_cast<__nv_bfloat162*>(&xh));
                    float2 l2 = __bfloat1622float2(*reinterpret_cast<__nv_bfloat162*>(&xl));
                    *reinterpret_cast<float2*>(out + grow * 64 + c) =
                        make_float2(u0 + (h2.x + l2.x), u1 + (h2.y + l2.y));
                }
            }
    }
}

// ---------------------------------------------------------------------------
extern "C" void kernel_launch(void* const* d_in, const int* in_sizes, int n_in,
                              void* d_out, int out_size) {
    (void)in_sizes; (void)n_in; (void)out_size;
    const float* x      = (const float*)d_in[0];
    const float* w_m1   = (const float*)d_in[1];
    const float* b_m1   = (const float*)d_in[2];
    const float* w_m2   = (const float*)d_in[3];
    const float* b_m2   = (const float*)d_in[4];
    const float* W_skip = (const float*)d_in[5];
    const float* b_skip = (const float*)d_in[6];
    const float* W_u1   = (const float*)d_in[7];
    const float* b_u1   = (const float*)d_in[8];
    const float* g1     = (const float*)d_in[9];
    const float* beta1  = (const float*)d_in[10];
    const float* rm1    = (const float*)d_in[11];
    const float* rv1    = (const float*)d_in[12];
    const float* W_u2   = (const float*)d_in[13];
    const float* b_u2   = (const float*)d_in[14];
    const float* g2     = (const float*)d_in[15];
    const float* beta2  = (const float*)d_in[16];
    const float* rm2    = (const float*)d_in[17];
    const float* rv2    = (const float*)d_in[18];
    float* out = (float*)d_out;

    cudaFuncSetAttribute(kernelA, cudaFuncAttributeMaxDynamicSharedMemorySize, SMEM_BYTES);
    cudaFuncSetAttribute(kernelC, cudaFuncAttributeMaxDynamicSharedMemorySize, SMEM_BYTES);
    cudaFuncSetAttribute(kernelBall, cudaFuncAttributeMaxDynamicSharedMemorySize, 65536);

    kernelW<<<dim3(16, 7), 256>>>(w_m1, w_m2, W_skip, W_u1, W_u2);

    kernelA<<<N_TOTAL / 128, 128, SMEM_BYTES>>>(x, b_m1, b_m2);

    // fused kernelB: all 4 block-size variants, longest first (5248 CTAs)
    kernelBall<<<5248, 256, 65536>>>();

    kernelC<<<N_TOTAL / 128, 128, SMEM_BYTES>>>(x, b_skip, b_u1, g1, beta1, rm1, rv1,
                                                b_u2, g2, beta2, rm2, rv2, out);
}